// round 4
// baseline (speedup 1.0000x reference)
#include <cuda_runtime.h>

// VectorQuantizer: for each of 16384 rows (z transposed to (n,256)), find
// argmin_k ||z - c_k||^2 over 2048 codes, emit q = z + fl(c_k - z) in
// (b,d,h,w) layout, plus loss scalars. Exact fp32 replication of:
//   dist = fl( fl(z2 + c2) - 2*dot ),  argmin first-index tie-break.

#define NUM_K   2048
#define DIMS    256
#define Q_ELEMS (16 * 256 * 1024)   // 4194304

// device scratch (no allocation allowed)
__device__ float  g_ct[DIMS * NUM_K];   // transposed codebook: g_ct[d*2048 + k]
__device__ float  g_c2[NUM_K];          // codebook row sum-of-squares
__device__ double g_partial[128];       // per-block loss partials

// dynamic smem layout (bytes)
#define OFF_AS   0                       // float As[256][128]        = 131072
#define OFF_BS   131072                  // float Bs2[2][32][264]     =  67584
#define BS_FLTS  (32 * 264)              // floats per buffer (8448)
#define OFF_Z2   198656                  // float z2s[128]            =    512
#define OFF_IDX  199168                  // int   idxs[128]           =    512
#define OFF_LR   199680                  // double lred[8]            =     64
#define SMEM_BYTES 199744

__device__ __forceinline__ void fma2(unsigned long long& d,
                                     unsigned long long a,
                                     unsigned long long b) {
    asm("fma.rn.f32x2 %0, %1, %2, %0;" : "+l"(d) : "l"(a), "l"(b));
}
__device__ __forceinline__ float lo32(unsigned long long v) {
    return __uint_as_float((unsigned)(v & 0xffffffffULL));
}
__device__ __forceinline__ float hi32(unsigned long long v) {
    return __uint_as_float((unsigned)(v >> 32));
}

// ---------------------------------------------------------------------------
// Kernel 1: transpose codebook (2048x256) -> g_ct[d][k]
// ---------------------------------------------------------------------------
__global__ void vq_transpose(const float* __restrict__ cb) {
    __shared__ float t[32][33];
    int kb = blockIdx.x * 32;
    int db = blockIdx.y * 32;
    int tx = threadIdx.x, ty = threadIdx.y;
#pragma unroll
    for (int i = ty; i < 32; i += 8)
        t[i][tx] = cb[(size_t)(kb + i) * DIMS + db + tx];
    __syncthreads();
#pragma unroll
    for (int i = ty; i < 32; i += 8)
        g_ct[(size_t)(db + i) * NUM_K + kb + tx] = t[tx][i];
}

// ---------------------------------------------------------------------------
// Kernel 2: codebook sum-of-squares (squares rounded separately, like jnp)
// ---------------------------------------------------------------------------
__global__ void vq_c2(const float* __restrict__ cb) {
    int warp = threadIdx.x >> 5;
    int lane = threadIdx.x & 31;
    int row  = blockIdx.x * 8 + warp;
    float s = 0.f;
#pragma unroll
    for (int q = 0; q < 8; ++q) {
        float v = cb[(size_t)row * DIMS + lane + q * 32];
        s = __fadd_rn(s, __fmul_rn(v, v));
    }
#pragma unroll
    for (int o = 16; o > 0; o >>= 1)
        s += __shfl_down_sync(0xffffffffu, s, o);
    if (lane == 0) g_c2[row] = s;
}

// ---------------------------------------------------------------------------
// Kernel 3: main — distance GEMM (f32x2 FMA) + argmin + gather + loss partials
// grid = 128 x 256 threads, ~195KB dynamic smem, 1 CTA/SM
// ---------------------------------------------------------------------------
__global__ void __launch_bounds__(256, 1)
vq_main(const float* __restrict__ z, const float* __restrict__ cb,
        float* __restrict__ out)
{
    extern __shared__ char sm[];
    float (*As)[128] = reinterpret_cast<float (*)[128]>(sm + OFF_AS);
    float*  bs2  = reinterpret_cast<float*>(sm + OFF_BS);
    float*  z2s  = reinterpret_cast<float*>(sm + OFF_Z2);
    int*    idxs = reinterpret_cast<int*>(sm + OFF_IDX);
    double* lred = reinterpret_cast<double*>(sm + OFF_LR);

    const int tid = threadIdx.x;
    const int tx  = tid & 15;       // 16 col-groups
    const int ty  = tid >> 4;       // 16 row-groups
    const int n0  = blockIdx.x * 128;
    const float* zb   = z   + (size_t)(n0 >> 10) * 262144 + (n0 & 1023);
    float*       outb = out + (size_t)(n0 >> 10) * 262144 + (n0 & 1023);

    // ---- load z tile into smem: As[d][r] (fully coalesced float4) ----
    for (int i = tid; i < 8192; i += 256) {
        int d = i >> 5, r4 = i & 31;
        float4 v = *reinterpret_cast<const float4*>(zb + (size_t)d * 1024 + r4 * 4);
        *reinterpret_cast<float4*>(&As[d][r4 * 4]) = v;
    }
    __syncthreads();

    // ---- per-row sum of squares ----
    if (tid < 128) {
        float s = 0.f;
#pragma unroll 8
        for (int d = 0; d < DIMS; ++d)
            s = __fadd_rn(s, __fmul_rn(As[d][tid], As[d][tid]));
        z2s[tid] = s;
    }
    __syncthreads();

    // this thread's 8 rows: ri 0..3 -> ty*4+ri ; ri 4..7 -> ty*4+64+(ri-4)
    float zz[8];
#pragma unroll
    for (int ri = 0; ri < 8; ++ri)
        zz[ri] = z2s[ty * 4 + (ri < 4 ? ri : ri + 60)];

    float minv[8];
    int   mini[8];
#pragma unroll
    for (int ri = 0; ri < 8; ++ri) { minv[ri] = 3.4e38f; mini[ri] = 0; }

    // prefetch lane mapping: each thread owns 4 float4 per 32x128 chunk
    const int dk0 = tid >> 5;   // 0..7
    const int c40 = tid & 31;   // 0..31
    float4 pf[4];

    // prologue: chunk m=0 (jt=0, dc=0) -> buffer 0 (duplicated layout)
    {
        const float* ctb = g_ct;   // + dc*32*NUM_K + jt*128 = 0
#pragma unroll
        for (int t = 0; t < 4; ++t)
            pf[t] = *reinterpret_cast<const float4*>(
                ctb + (size_t)(dk0 + 8 * t) * NUM_K + c40 * 4);
#pragma unroll
        for (int t = 0; t < 4; ++t) {
            float* br = bs2 + (dk0 + 8 * t) * 264 + c40 * 8;
            float4 v = pf[t];
            *reinterpret_cast<float4*>(br)     = make_float4(v.x, v.x, v.y, v.y);
            *reinterpret_cast<float4*>(br + 4) = make_float4(v.z, v.z, v.w, v.w);
        }
    }
    __syncthreads();

    unsigned long long acc[4][8];

    // 128 chunks: m -> (k-tile jt = m>>3, d-chunk dc = m&7)
    for (int m = 0; m < 128; ++m) {
        const int cur = m & 1;
        const int jt  = m >> 3;
        const int dc  = m & 7;

        // prefetch next chunk (global -> regs)
        if (m < 127) {
            const int m1 = m + 1;
            const float* ctb = g_ct + (size_t)((m1 & 7) * 32) * NUM_K + (m1 >> 3) * 128;
#pragma unroll
            for (int t = 0; t < 4; ++t)
                pf[t] = *reinterpret_cast<const float4*>(
                    ctb + (size_t)(dk0 + 8 * t) * NUM_K + c40 * 4);
        }

        if (dc == 0) {
#pragma unroll
            for (int rp = 0; rp < 4; ++rp)
#pragma unroll
                for (int c = 0; c < 8; ++c) acc[rp][c] = 0ULL;
        }

        // ---- compute: 32 d-steps of 8x8 microtile, packed f32x2 FMA ----
        const float* bbuf = bs2 + cur * BS_FLTS;
#pragma unroll 4
        for (int dk = 0; dk < 32; ++dk) {
            const int d = dc * 32 + dk;
            ulonglong2 a01 = *reinterpret_cast<const ulonglong2*>(&As[d][ty * 4]);
            ulonglong2 a23 = *reinterpret_cast<const ulonglong2*>(&As[d][ty * 4 + 64]);
            const float* brow = bbuf + dk * 264;
            ulonglong2 u0 = *reinterpret_cast<const ulonglong2*>(brow + tx * 8);
            ulonglong2 u1 = *reinterpret_cast<const ulonglong2*>(brow + tx * 8 + 4);
            ulonglong2 u2 = *reinterpret_cast<const ulonglong2*>(brow + 128 + tx * 8);
            ulonglong2 u3 = *reinterpret_cast<const ulonglong2*>(brow + 128 + tx * 8 + 4);
            unsigned long long ar[4] = {a01.x, a01.y, a23.x, a23.y};
            unsigned long long bv[8] = {u0.x, u0.y, u1.x, u1.y, u2.x, u2.y, u3.x, u3.y};
#pragma unroll
            for (int rp = 0; rp < 4; ++rp)
#pragma unroll
                for (int c = 0; c < 8; ++c)
                    fma2(acc[rp][c], ar[rp], bv[c]);
        }

        // store prefetched chunk duplicated into the other buffer
        if (m < 127) {
            float* bp = bs2 + (cur ^ 1) * BS_FLTS;
#pragma unroll
            for (int t = 0; t < 4; ++t) {
                float* br = bp + (dk0 + 8 * t) * 264 + c40 * 8;
                float4 v = pf[t];
                *reinterpret_cast<float4*>(br)     = make_float4(v.x, v.x, v.y, v.y);
                *reinterpret_cast<float4*>(br + 4) = make_float4(v.z, v.z, v.w, v.w);
            }
        }
        __syncthreads();

        // ---- k-tile epilogue: dist = fl(fl(z2+c2) - 2*dot), strict < ----
        if (dc == 7) {
            const int j0 = jt * 128;
            float c2v[8];
#pragma unroll
            for (int c = 0; c < 8; ++c)
                c2v[c] = g_c2[j0 + tx * 4 + (c & 3) + ((c >> 2) << 6)];
#pragma unroll
            for (int rp = 0; rp < 4; ++rp) {
#pragma unroll
                for (int c = 0; c < 8; ++c) {
                    const int j = j0 + tx * 4 + (c & 3) + ((c >> 2) << 6);
                    const int r0 = rp * 2, r1 = rp * 2 + 1;
                    float d0 = __fsub_rn(__fadd_rn(zz[r0], c2v[c]),
                                         __fmul_rn(2.0f, lo32(acc[rp][c])));
                    if (d0 < minv[r0]) { minv[r0] = d0; mini[r0] = j; }
                    float d1 = __fsub_rn(__fadd_rn(zz[r1], c2v[c]),
                                         __fmul_rn(2.0f, hi32(acc[rp][c])));
                    if (d1 < minv[r1]) { minv[r1] = d1; mini[r1] = j; }
                }
            }
        }
    }

    // ---- cross-thread argmin reduce (16 tx-lanes per row group) ----
#pragma unroll
    for (int ri = 0; ri < 8; ++ri) {
        float v = minv[ri];
        int   id = mini[ri];
#pragma unroll
        for (int off = 8; off > 0; off >>= 1) {
            float v2 = __shfl_down_sync(0xffffffffu, v, off, 16);
            int   i2 = __shfl_down_sync(0xffffffffu, id, off, 16);
            if (v2 < v || (v2 == v && i2 < id)) { v = v2; id = i2; }
        }
        if (tx == 0)
            idxs[ty * 4 + (ri < 4 ? ri : ri + 60)] = id;
    }
    __syncthreads();

    // ---- output q = fl(z + fl(c - z)) (coalesced) + fp64 loss partial ----
    double ls = 0.0;
    for (int i = tid; i < 8192; i += 256) {
        int d = i >> 5, r4 = i & 31;
        float4 zv = *reinterpret_cast<const float4*>(&As[d][r4 * 4]);
        int i0 = idxs[r4 * 4 + 0], i1 = idxs[r4 * 4 + 1];
        int i2 = idxs[r4 * 4 + 2], i3 = idxs[r4 * 4 + 3];
        float c0 = cb[(size_t)i0 * DIMS + d];
        float c1 = cb[(size_t)i1 * DIMS + d];
        float c2 = cb[(size_t)i2 * DIMS + d];
        float c3 = cb[(size_t)i3 * DIMS + d];
        float e0 = __fsub_rn(c0, zv.x), e1 = __fsub_rn(c1, zv.y);
        float e2 = __fsub_rn(c2, zv.z), e3 = __fsub_rn(c3, zv.w);
        float4 qv = make_float4(__fadd_rn(zv.x, e0), __fadd_rn(zv.y, e1),
                                __fadd_rn(zv.z, e2), __fadd_rn(zv.w, e3));
        ls += (double)e0 * e0 + (double)e1 * e1
            + (double)e2 * e2 + (double)e3 * e3;
        *reinterpret_cast<float4*>(outb + (size_t)d * 1024 + r4 * 4) = qv;
    }
#pragma unroll
    for (int o = 16; o > 0; o >>= 1)
        ls += __shfl_down_sync(0xffffffffu, ls, o);
    if ((tid & 31) == 0) lred[tid >> 5] = ls;
    __syncthreads();
    if (tid == 0) {
        double s = 0.0;
#pragma unroll
        for (int w = 0; w < 8; ++w) s += lred[w];
        g_partial[blockIdx.x] = s;
    }
}

// ---------------------------------------------------------------------------
// Kernel 4: finalize losses
// ---------------------------------------------------------------------------
__global__ void vq_final(float* __restrict__ out, int out_size) {
    __shared__ double sp[4];
    int t = threadIdx.x;               // 128 threads
    double v = g_partial[t];
#pragma unroll
    for (int o = 16; o > 0; o >>= 1)
        v += __shfl_down_sync(0xffffffffu, v, o);
    if ((t & 31) == 0) sp[t >> 5] = v;
    __syncthreads();
    if (t == 0) {
        double s = sp[0] + sp[1] + sp[2] + sp[3];
        double mse = s / (double)Q_ELEMS;
        if (out_size >= Q_ELEMS + 3) {
            out[Q_ELEMS + 0] = (float)(mse * 1.25);  // loss = cb + 0.25*commit
            out[Q_ELEMS + 1] = (float)mse;           // codebook_loss
            out[Q_ELEMS + 2] = (float)mse;           // commitment_loss (== mse)
        }
    }
}

extern "C" void kernel_launch(void* const* d_in, const int* in_sizes, int n_in,
                              void* d_out, int out_size) {
    (void)in_sizes; (void)n_in;
    const float* z  = (const float*)d_in[0];
    const float* cb = (const float*)d_in[1];
    float* out = (float*)d_out;

    cudaFuncSetAttribute(vq_main, cudaFuncAttributeMaxDynamicSharedMemorySize,
                         SMEM_BYTES);

    vq_transpose<<<dim3(64, 8), dim3(32, 8)>>>(cb);
    vq_c2<<<256, 256>>>(cb);
    vq_main<<<128, 256, SMEM_BYTES>>>(z, cb, out);
    vq_final<<<1, 128>>>(out, out_size);
}

// round 5
// speedup vs baseline: 1.0001x; 1.0001x over previous
#include <cuda_runtime.h>

// VectorQuantizer: for each of 16384 rows (z transposed to (n,256)), find
// argmin_k ||z - c_k||^2 over 2048 codes, emit q = z + fl(c_k - z) in
// (b,d,h,w) layout, plus loss scalars. Exact fp32 replication of:
//   dist = fl( fl(z2 + c2) - 2*dot ),  argmin first-index tie-break.

#define NUM_K   2048
#define DIMS    256
#define Q_ELEMS (16 * 256 * 1024)   // 4194304

// device scratch (no allocation allowed)
__device__ float  g_ct[DIMS * NUM_K];   // transposed codebook: g_ct[d*2048 + k]
__device__ float  g_c2[NUM_K];          // codebook row sum-of-squares
__device__ double g_partial[128];       // per-block loss partials

// dynamic smem layout (bytes)
#define OFF_AS   0                       // float As[256][128]        = 131072
#define OFF_BS   131072                  // float Bs2[2][32][264]     =  67584
#define BS_FLTS  (32 * 264)              // floats per buffer (8448)
#define OFF_Z2   198656                  // float z2s[128]            =    512
#define OFF_IDX  199168                  // int   idxs[128]           =    512
#define OFF_LR   199680                  // double lred[8]            =     64
#define SMEM_BYTES 199744

__device__ __forceinline__ void fma2(unsigned long long& d,
                                     unsigned long long a,
                                     unsigned long long b) {
    asm("fma.rn.f32x2 %0, %1, %2, %0;" : "+l"(d) : "l"(a), "l"(b));
}
__device__ __forceinline__ float lo32(unsigned long long v) {
    return __uint_as_float((unsigned)(v & 0xffffffffULL));
}
__device__ __forceinline__ float hi32(unsigned long long v) {
    return __uint_as_float((unsigned)(v >> 32));
}

// ---------------------------------------------------------------------------
// Kernel 1: transpose codebook (2048x256) -> g_ct[d][k]
// ---------------------------------------------------------------------------
__global__ void vq_transpose(const float* __restrict__ cb) {
    __shared__ float t[32][33];
    int kb = blockIdx.x * 32;
    int db = blockIdx.y * 32;
    int tx = threadIdx.x, ty = threadIdx.y;
#pragma unroll
    for (int i = ty; i < 32; i += 8)
        t[i][tx] = cb[(size_t)(kb + i) * DIMS + db + tx];
    __syncthreads();
#pragma unroll
    for (int i = ty; i < 32; i += 8)
        g_ct[(size_t)(db + i) * NUM_K + kb + tx] = t[tx][i];
}

// ---------------------------------------------------------------------------
// Kernel 2: codebook sum-of-squares (squares rounded separately, like jnp)
// ---------------------------------------------------------------------------
__global__ void vq_c2(const float* __restrict__ cb) {
    int warp = threadIdx.x >> 5;
    int lane = threadIdx.x & 31;
    int row  = blockIdx.x * 8 + warp;
    float s = 0.f;
#pragma unroll
    for (int q = 0; q < 8; ++q) {
        float v = cb[(size_t)row * DIMS + lane + q * 32];
        s = __fadd_rn(s, __fmul_rn(v, v));
    }
#pragma unroll
    for (int o = 16; o > 0; o >>= 1)
        s += __shfl_down_sync(0xffffffffu, s, o);
    if (lane == 0) g_c2[row] = s;
}

// ---------------------------------------------------------------------------
// Kernel 3: main — distance GEMM (f32x2 FMA) + argmin + gather + loss partials
// grid = 128 x 256 threads, ~195KB dynamic smem, 1 CTA/SM
// ---------------------------------------------------------------------------
__global__ void __launch_bounds__(256, 1)
vq_main(const float* __restrict__ z, const float* __restrict__ cb,
        float* __restrict__ out)
{
    extern __shared__ char sm[];
    float (*As)[128] = reinterpret_cast<float (*)[128]>(sm + OFF_AS);
    float*  bs2  = reinterpret_cast<float*>(sm + OFF_BS);
    float*  z2s  = reinterpret_cast<float*>(sm + OFF_Z2);
    int*    idxs = reinterpret_cast<int*>(sm + OFF_IDX);
    double* lred = reinterpret_cast<double*>(sm + OFF_LR);

    const int tid = threadIdx.x;
    const int tx  = tid & 15;       // 16 col-groups
    const int ty  = tid >> 4;       // 16 row-groups
    const int n0  = blockIdx.x * 128;
    const float* zb   = z   + (size_t)(n0 >> 10) * 262144 + (n0 & 1023);
    float*       outb = out + (size_t)(n0 >> 10) * 262144 + (n0 & 1023);

    // ---- load z tile into smem: As[d][r] (fully coalesced float4) ----
    for (int i = tid; i < 8192; i += 256) {
        int d = i >> 5, r4 = i & 31;
        float4 v = *reinterpret_cast<const float4*>(zb + (size_t)d * 1024 + r4 * 4);
        *reinterpret_cast<float4*>(&As[d][r4 * 4]) = v;
    }
    __syncthreads();

    // ---- per-row sum of squares ----
    if (tid < 128) {
        float s = 0.f;
#pragma unroll 8
        for (int d = 0; d < DIMS; ++d)
            s = __fadd_rn(s, __fmul_rn(As[d][tid], As[d][tid]));
        z2s[tid] = s;
    }
    __syncthreads();

    // this thread's 8 rows: ri 0..3 -> ty*4+ri ; ri 4..7 -> ty*4+64+(ri-4)
    float zz[8];
#pragma unroll
    for (int ri = 0; ri < 8; ++ri)
        zz[ri] = z2s[ty * 4 + (ri < 4 ? ri : ri + 60)];

    float minv[8];
    int   mini[8];
#pragma unroll
    for (int ri = 0; ri < 8; ++ri) { minv[ri] = 3.4e38f; mini[ri] = 0; }

    // prefetch lane mapping: each thread owns 4 float4 per 32x128 chunk
    const int dk0 = tid >> 5;   // 0..7
    const int c40 = tid & 31;   // 0..31
    float4 pf[4];

    // prologue: chunk m=0 (jt=0, dc=0) -> buffer 0 (duplicated layout)
    {
        const float* ctb = g_ct;   // + dc*32*NUM_K + jt*128 = 0
#pragma unroll
        for (int t = 0; t < 4; ++t)
            pf[t] = *reinterpret_cast<const float4*>(
                ctb + (size_t)(dk0 + 8 * t) * NUM_K + c40 * 4);
#pragma unroll
        for (int t = 0; t < 4; ++t) {
            float* br = bs2 + (dk0 + 8 * t) * 264 + c40 * 8;
            float4 v = pf[t];
            *reinterpret_cast<float4*>(br)     = make_float4(v.x, v.x, v.y, v.y);
            *reinterpret_cast<float4*>(br + 4) = make_float4(v.z, v.z, v.w, v.w);
        }
    }
    __syncthreads();

    unsigned long long acc[4][8];

    // 128 chunks: m -> (k-tile jt = m>>3, d-chunk dc = m&7)
    for (int m = 0; m < 128; ++m) {
        const int cur = m & 1;
        const int jt  = m >> 3;
        const int dc  = m & 7;

        // prefetch next chunk (global -> regs)
        if (m < 127) {
            const int m1 = m + 1;
            const float* ctb = g_ct + (size_t)((m1 & 7) * 32) * NUM_K + (m1 >> 3) * 128;
#pragma unroll
            for (int t = 0; t < 4; ++t)
                pf[t] = *reinterpret_cast<const float4*>(
                    ctb + (size_t)(dk0 + 8 * t) * NUM_K + c40 * 4);
        }

        if (dc == 0) {
#pragma unroll
            for (int rp = 0; rp < 4; ++rp)
#pragma unroll
                for (int c = 0; c < 8; ++c) acc[rp][c] = 0ULL;
        }

        // ---- compute: 32 d-steps of 8x8 microtile, packed f32x2 FMA ----
        const float* bbuf = bs2 + cur * BS_FLTS;
#pragma unroll 4
        for (int dk = 0; dk < 32; ++dk) {
            const int d = dc * 32 + dk;
            ulonglong2 a01 = *reinterpret_cast<const ulonglong2*>(&As[d][ty * 4]);
            ulonglong2 a23 = *reinterpret_cast<const ulonglong2*>(&As[d][ty * 4 + 64]);
            const float* brow = bbuf + dk * 264;
            ulonglong2 u0 = *reinterpret_cast<const ulonglong2*>(brow + tx * 8);
            ulonglong2 u1 = *reinterpret_cast<const ulonglong2*>(brow + tx * 8 + 4);
            ulonglong2 u2 = *reinterpret_cast<const ulonglong2*>(brow + 128 + tx * 8);
            ulonglong2 u3 = *reinterpret_cast<const ulonglong2*>(brow + 128 + tx * 8 + 4);
            unsigned long long ar[4] = {a01.x, a01.y, a23.x, a23.y};
            unsigned long long bv[8] = {u0.x, u0.y, u1.x, u1.y, u2.x, u2.y, u3.x, u3.y};
#pragma unroll
            for (int rp = 0; rp < 4; ++rp)
#pragma unroll
                for (int c = 0; c < 8; ++c)
                    fma2(acc[rp][c], ar[rp], bv[c]);
        }

        // store prefetched chunk duplicated into the other buffer
        if (m < 127) {
            float* bp = bs2 + (cur ^ 1) * BS_FLTS;
#pragma unroll
            for (int t = 0; t < 4; ++t) {
                float* br = bp + (dk0 + 8 * t) * 264 + c40 * 8;
                float4 v = pf[t];
                *reinterpret_cast<float4*>(br)     = make_float4(v.x, v.x, v.y, v.y);
                *reinterpret_cast<float4*>(br + 4) = make_float4(v.z, v.z, v.w, v.w);
            }
        }
        __syncthreads();

        // ---- k-tile epilogue: dist = fl(fl(z2+c2) - 2*dot), strict < ----
        if (dc == 7) {
            const int j0 = jt * 128;
            float c2v[8];
#pragma unroll
            for (int c = 0; c < 8; ++c)
                c2v[c] = g_c2[j0 + tx * 4 + (c & 3) + ((c >> 2) << 6)];
#pragma unroll
            for (int rp = 0; rp < 4; ++rp) {
#pragma unroll
                for (int c = 0; c < 8; ++c) {
                    const int j = j0 + tx * 4 + (c & 3) + ((c >> 2) << 6);
                    const int r0 = rp * 2, r1 = rp * 2 + 1;
                    float d0 = __fsub_rn(__fadd_rn(zz[r0], c2v[c]),
                                         __fmul_rn(2.0f, lo32(acc[rp][c])));
                    if (d0 < minv[r0]) { minv[r0] = d0; mini[r0] = j; }
                    float d1 = __fsub_rn(__fadd_rn(zz[r1], c2v[c]),
                                         __fmul_rn(2.0f, hi32(acc[rp][c])));
                    if (d1 < minv[r1]) { minv[r1] = d1; mini[r1] = j; }
                }
            }
        }
    }

    // ---- cross-thread argmin reduce (16 tx-lanes per row group) ----
#pragma unroll
    for (int ri = 0; ri < 8; ++ri) {
        float v = minv[ri];
        int   id = mini[ri];
#pragma unroll
        for (int off = 8; off > 0; off >>= 1) {
            float v2 = __shfl_down_sync(0xffffffffu, v, off, 16);
            int   i2 = __shfl_down_sync(0xffffffffu, id, off, 16);
            if (v2 < v || (v2 == v && i2 < id)) { v = v2; id = i2; }
        }
        if (tx == 0)
            idxs[ty * 4 + (ri < 4 ? ri : ri + 60)] = id;
    }
    __syncthreads();

    // ---- output q = fl(z + fl(c - z)) (coalesced) + fp64 loss partial ----
    double ls = 0.0;
    for (int i = tid; i < 8192; i += 256) {
        int d = i >> 5, r4 = i & 31;
        float4 zv = *reinterpret_cast<const float4*>(&As[d][r4 * 4]);
        int i0 = idxs[r4 * 4 + 0], i1 = idxs[r4 * 4 + 1];
        int i2 = idxs[r4 * 4 + 2], i3 = idxs[r4 * 4 + 3];
        float c0 = cb[(size_t)i0 * DIMS + d];
        float c1 = cb[(size_t)i1 * DIMS + d];
        float c2 = cb[(size_t)i2 * DIMS + d];
        float c3 = cb[(size_t)i3 * DIMS + d];
        float e0 = __fsub_rn(c0, zv.x), e1 = __fsub_rn(c1, zv.y);
        float e2 = __fsub_rn(c2, zv.z), e3 = __fsub_rn(c3, zv.w);
        float4 qv = make_float4(__fadd_rn(zv.x, e0), __fadd_rn(zv.y, e1),
                                __fadd_rn(zv.z, e2), __fadd_rn(zv.w, e3));
        ls += (double)e0 * e0 + (double)e1 * e1
            + (double)e2 * e2 + (double)e3 * e3;
        *reinterpret_cast<float4*>(outb + (size_t)d * 1024 + r4 * 4) = qv;
    }
#pragma unroll
    for (int o = 16; o > 0; o >>= 1)
        ls += __shfl_down_sync(0xffffffffu, ls, o);
    if ((tid & 31) == 0) lred[tid >> 5] = ls;
    __syncthreads();
    if (tid == 0) {
        double s = 0.0;
#pragma unroll
        for (int w = 0; w < 8; ++w) s += lred[w];
        g_partial[blockIdx.x] = s;
    }
}

// ---------------------------------------------------------------------------
// Kernel 4: finalize losses
// ---------------------------------------------------------------------------
__global__ void vq_final(float* __restrict__ out, int out_size) {
    __shared__ double sp[4];
    int t = threadIdx.x;               // 128 threads
    double v = g_partial[t];
#pragma unroll
    for (int o = 16; o > 0; o >>= 1)
        v += __shfl_down_sync(0xffffffffu, v, o);
    if ((t & 31) == 0) sp[t >> 5] = v;
    __syncthreads();
    if (t == 0) {
        double s = sp[0] + sp[1] + sp[2] + sp[3];
        double mse = s / (double)Q_ELEMS;
        if (out_size >= Q_ELEMS + 3) {
            out[Q_ELEMS + 0] = (float)(mse * 1.25);  // loss = cb + 0.25*commit
            out[Q_ELEMS + 1] = (float)mse;           // codebook_loss
            out[Q_ELEMS + 2] = (float)mse;           // commitment_loss (== mse)
        }
    }
}

extern "C" void kernel_launch(void* const* d_in, const int* in_sizes, int n_in,
                              void* d_out, int out_size) {
    (void)in_sizes; (void)n_in;
    const float* z  = (const float*)d_in[0];
    const float* cb = (const float*)d_in[1];
    float* out = (float*)d_out;

    cudaFuncSetAttribute(vq_main, cudaFuncAttributeMaxDynamicSharedMemorySize,
                         SMEM_BYTES);

    vq_transpose<<<dim3(64, 8), dim3(32, 8)>>>(cb);
    vq_c2<<<256, 256>>>(cb);
    vq_main<<<128, 256, SMEM_BYTES>>>(z, cb, out);
    vq_final<<<1, 128>>>(out, out_size);
}